// round 7
// baseline (speedup 1.0000x reference)
#include <cuda_runtime.h>
#include <cuda_bf16.h>
#include <math.h>

#define Nn   100000
#define Ee   1600000
#define ETOT (Ee + Nn)
#define DINq 16
#define Hq   128
#define HEADSq 4
#define DOUTq  32
#define Gq   64
#define FOUTq 256
#define NTILE ((Nn + 255) / 256)

typedef unsigned long long u64;
typedef unsigned int u32;

// ---- scratch (static device memory) ----
__device__ float g_h[(size_t)Nn * Hq];
__device__ u32   g_hpb[(size_t)Nn * (Hq / 2)];
__device__ float g_alS[Nn * HEADSq];
__device__ float g_alD[Nn * HEADSq];
__device__ int   g_cnt_i[Nn];
__device__ int   g_rowptr[Nn + 1];
__device__ int   g_cursor[Nn];
__device__ int   g_csr_src[ETOT];
__device__ u64   g_tstat[NTILE];
__device__ float g_psum[Gq * Hq];
__device__ float g_pmax[Gq * Hq];
__device__ float g_gcnt[Gq];

#define FLAG_AGG (1ull << 62)
#define FLAG_INC (1ull << 63)

__device__ __forceinline__ void atomicMaxFloat(float* addr, float v) {
    if (v >= 0.0f) atomicMax((int*)addr, __float_as_int(v));
    else           atomicMin((unsigned int*)addr, __float_as_uint(v));
}

__device__ __forceinline__ float gelu_exact(float v) {
    return 0.5f * v * (1.0f + erff(v * 0.70710678118654752f));
}

// ---- packed f32x2 helpers (Blackwell FFMA2) ----
__device__ __forceinline__ void pfma(u64& d, u64 a, u64 b) {
    asm("fma.rn.f32x2 %0, %1, %2, %0;" : "+l"(d) : "l"(a), "l"(b));
}
__device__ __forceinline__ u64 pku(u32 lo, u32 hi) {
    u64 r; asm("mov.b64 %0, {%1,%2};" : "=l"(r) : "r"(lo), "r"(hi)); return r;
}
__device__ __forceinline__ u64 swap64(u64 p) {
    return pku((u32)(p >> 32), (u32)p);
}
__device__ __forceinline__ float lo32(u64 p) { return __uint_as_float((u32)p); }
__device__ __forceinline__ float hi32(u64 p) { return __uint_as_float((u32)(p >> 32)); }
__device__ __forceinline__ u32 bfpack(float lo, float hi) {
    u32 r; asm("cvt.rn.bf16x2.f32 %0, %1, %2;" : "=r"(r) : "f"(hi), "f"(lo)); return r;
}

// ------- tiled GEMM: [M x 128] = A[M x K] @ W[K x 128], 8x8/thread FFMA2 -------
template<int K, bool DO_GELU, bool DO_ATTN, bool OUT_BF16>
__global__ void gemm128T(const float* __restrict__ A, const float* __restrict__ W,
                         const float* __restrict__ bias,
                         const float* __restrict__ a_s, const float* __restrict__ a_d,
                         float* __restrict__ C, int M)
{
    const int BN = 128, BK = 16;
    __shared__ float As[BK][BN + 4];
    __shared__ float Ws[BK][Hq + 4];
    int tid = threadIdx.x;            // 256 threads
    int tx = tid & 15, ty = tid >> 4;
    int lane = tid & 31;
    int m0 = blockIdx.x * BN;
    int c0 = tx * 8;
    int r0 = ty * 8;

    u64 acc[4][4][2];
#pragma unroll
    for (int rp = 0; rp < 4; rp++)
#pragma unroll
        for (int cp = 0; cp < 4; cp++) { acc[rp][cp][0] = 0ull; acc[rp][cp][1] = 0ull; }

    for (int k0 = 0; k0 < K; k0 += BK) {
#pragma unroll
        for (int i = tid; i < BN * BK; i += 256) {
            int r = i >> 4, k = i & 15;
            As[k][r] = (m0 + r < M) ? A[(size_t)(m0 + r) * K + k0 + k] : 0.f;
        }
#pragma unroll
        for (int i = tid; i < BK * Hq; i += 256) {
            int k = i >> 7, c = i & 127;
            Ws[k][c] = W[(size_t)(k0 + k) * Hq + c];
        }
        __syncthreads();
#pragma unroll
        for (int kk = 0; kk < BK; kk++) {
            ulonglong2 ra = *(const ulonglong2*)&As[kk][r0];
            ulonglong2 rb = *(const ulonglong2*)&As[kk][r0 + 4];
            ulonglong2 wa = *(const ulonglong2*)&Ws[kk][c0];
            ulonglong2 wb = *(const ulonglong2*)&Ws[kk][c0 + 4];
            u64 rr[4] = {ra.x, ra.y, rb.x, rb.y};
            u64 cn[4] = {wa.x, wa.y, wb.x, wb.y};
            u64 cs[4] = {swap64(wa.x), swap64(wa.y), swap64(wb.x), swap64(wb.y)};
#pragma unroll
            for (int rp = 0; rp < 4; rp++)
#pragma unroll
                for (int cp = 0; cp < 4; cp++) {
                    pfma(acc[rp][cp][0], rr[rp], cn[cp]);
                    pfma(acc[rp][cp][1], rr[rp], cs[cp]);
                }
        }
        __syncthreads();
    }

    float v[8][8];
#pragma unroll
    for (int rp = 0; rp < 4; rp++)
#pragma unroll
        for (int cp = 0; cp < 4; cp++) {
            v[2 * rp][2 * cp]         = lo32(acc[rp][cp][0]);
            v[2 * rp + 1][2 * cp + 1] = hi32(acc[rp][cp][0]);
            v[2 * rp][2 * cp + 1]     = lo32(acc[rp][cp][1]);
            v[2 * rp + 1][2 * cp]     = hi32(acc[rp][cp][1]);
        }

    if (DO_GELU) {
        float b8[8];
#pragma unroll
        for (int q = 0; q < 8; q++) b8[q] = bias[c0 + q];
#pragma unroll
        for (int r = 0; r < 8; r++) {
            int m = m0 + r0 + r;
            if (m < M) {
#pragma unroll
                for (int q = 0; q < 8; q++) v[r][q] = gelu_exact(v[r][q] + b8[q]);
                float4 o0 = make_float4(v[r][0], v[r][1], v[r][2], v[r][3]);
                float4 o1 = make_float4(v[r][4], v[r][5], v[r][6], v[r][7]);
                *(float4*)&C[(size_t)m * Hq + c0] = o0;
                *(float4*)&C[(size_t)m * Hq + c0 + 4] = o1;
            }
        }
    }

    if (OUT_BF16) {
#pragma unroll
        for (int r = 0; r < 8; r++) {
            int m = m0 + r0 + r;
            if (m < M) {
                uint4 o;
                o.x = bfpack(v[r][0], v[r][1]);
                o.y = bfpack(v[r][2], v[r][3]);
                o.z = bfpack(v[r][4], v[r][5]);
                o.w = bfpack(v[r][6], v[r][7]);
                *(uint4*)&g_hpb[(size_t)m * (Hq / 2) + tx * 4] = o;
            }
        }
    }

    if (DO_ATTN) {
        float as8[8], ad8[8];
#pragma unroll
        for (int q = 0; q < 8; q++) { as8[q] = a_s[c0 + q]; ad8[q] = a_d[c0 + q]; }
        int head = tx >> 2;
#pragma unroll
        for (int r = 0; r < 8; r++) {
            float ps = 0.f, pd = 0.f;
#pragma unroll
            for (int q = 0; q < 8; q++) { ps += v[r][q] * as8[q]; pd += v[r][q] * ad8[q]; }
            ps += __shfl_xor_sync(0xffffffffu, ps, 1);
            pd += __shfl_xor_sync(0xffffffffu, pd, 1);
            ps += __shfl_xor_sync(0xffffffffu, ps, 2);
            pd += __shfl_xor_sync(0xffffffffu, pd, 2);
            int m = m0 + r0 + r;
            if ((lane & 3) == 0 && m < M) {
                g_alS[m * 4 + head] = ps;
                g_alD[m * 4 + head] = pd;
            }
        }
    }
}

// ================= CSR build =================
__global__ void hist_dst(const int* __restrict__ ei)
{
    int e = blockIdx.x * blockDim.x + threadIdx.x;
    if (e >= ETOT) return;
    int d = (e < Ee) ? ei[Ee + e] : (e - Ee);
    atomicAdd(&g_cnt_i[d], 1);
}

// single-kernel exclusive scan via decoupled lookback (tiles of 256)
__global__ void scan_dl()
{
    __shared__ int s[256];
    __shared__ int s_prefix;
    int bid = blockIdx.x, tid = threadIdx.x;
    int i = bid * 256 + tid;
    int v = (i < Nn) ? g_cnt_i[i] : 0;
    s[tid] = v;
    __syncthreads();
#pragma unroll
    for (int o = 1; o < 256; o <<= 1) {
        int t = (tid >= o) ? s[tid - o] : 0;
        __syncthreads();
        s[tid] += t;
        __syncthreads();
    }
    int incl = s[tid];
    int agg  = s[255];

    if (tid == 0) {
        u64 pub = (bid == 0) ? (FLAG_INC | (u64)(u32)agg) : (FLAG_AGG | (u64)(u32)agg);
        atomicExch((unsigned long long*)&g_tstat[bid], pub);
        if (bid == 0) s_prefix = 0;
    }

    if (bid > 0 && tid < 32) {
        int lane = tid;
        u32 running = 0;
        int look = bid - 1;
        while (true) {
            int t = look - lane;
            u64 st;
            if (t >= 0) {
                do { st = *(volatile u64*)&g_tstat[t]; } while (st == 0);
            } else {
                st = FLAG_INC;  // virtual tile with value 0
            }
            u32 incm = __ballot_sync(0xffffffffu, (st & FLAG_INC) != 0);
            u32 val;
            if (incm) {
                int L = __ffs(incm) - 1;           // closest predecessor with INC
                val = (lane <= L) ? (u32)st : 0;
            } else {
                val = (u32)st;
            }
#pragma unroll
            for (int o = 16; o; o >>= 1) val += __shfl_xor_sync(0xffffffffu, val, o);
            running += val;
            if (incm) break;
            look -= 32;
        }
        if (lane == 0) {
            atomicExch((unsigned long long*)&g_tstat[bid],
                       FLAG_INC | (u64)(u32)(running + (u32)agg));
            s_prefix = (int)running;
        }
    }
    __syncthreads();

    int pre = s_prefix;
    if (i < Nn) {
        int r = pre + incl - v;   // exclusive
        g_rowptr[i] = r;
        g_cursor[i] = r;
    }
    if (i == 0) g_rowptr[Nn] = ETOT;
}

__global__ void csr_fill(const int* __restrict__ ei)
{
    int e = blockIdx.x * blockDim.x + threadIdx.x;
    if (e >= ETOT) return;
    int s, d;
    if (e < Ee) { s = ei[e]; d = ei[Ee + e]; } else { s = d = e - Ee; }
    int pos = atomicAdd(&g_cursor[d], 1);
    g_csr_src[pos] = s;
}

// == single-pass GAT aggregation (num/den together) + bias + residual + LN ==
__global__ void gat_agg_ln(const float* __restrict__ bg, const float* __restrict__ ga,
                           const float* __restrict__ be)
{
    int n = blockIdx.x * 8 + (threadIdx.x >> 5);
    if (n >= Nn) return;
    int lane = threadIdx.x & 31;
    int hd = lane >> 3;
    int start = g_rowptr[n];
    int end   = g_rowptr[n + 1];

    float adh = g_alD[n * 4 + hd];

    float a0 = 0.f, a1 = 0.f, a2 = 0.f, a3 = 0.f, den = 0.f;
    int i = start;
    for (; i + 3 < end; i += 4) {
        int s0 = g_csr_src[i];
        int s1 = g_csr_src[i + 1];
        int s2 = g_csr_src[i + 2];
        int s3 = g_csr_src[i + 3];
        float l0 = g_alS[s0 * 4 + hd] + adh;
        float l1 = g_alS[s1 * 4 + hd] + adh;
        float l2 = g_alS[s2 * 4 + hd] + adh;
        float l3 = g_alS[s3 * 4 + hd] + adh;
        l0 = (l0 > 0.f) ? l0 : 0.2f * l0;
        l1 = (l1 > 0.f) ? l1 : 0.2f * l1;
        l2 = (l2 > 0.f) ? l2 : 0.2f * l2;
        l3 = (l3 > 0.f) ? l3 : 0.2f * l3;
        float e0 = __expf(l0), e1 = __expf(l1), e2 = __expf(l2), e3 = __expf(l3);
        den += (e0 + e1) + (e2 + e3);
        uint2 p0 = *(const uint2*)&g_hpb[(size_t)s0 * (Hq / 2) + lane * 2];
        uint2 p1 = *(const uint2*)&g_hpb[(size_t)s1 * (Hq / 2) + lane * 2];
        uint2 p2 = *(const uint2*)&g_hpb[(size_t)s2 * (Hq / 2) + lane * 2];
        uint2 p3 = *(const uint2*)&g_hpb[(size_t)s3 * (Hq / 2) + lane * 2];
        a0 += e0 * __uint_as_float(p0.x << 16) + e1 * __uint_as_float(p1.x << 16)
            + e2 * __uint_as_float(p2.x << 16) + e3 * __uint_as_float(p3.x << 16);
        a1 += e0 * __uint_as_float(p0.x & 0xffff0000u) + e1 * __uint_as_float(p1.x & 0xffff0000u)
            + e2 * __uint_as_float(p2.x & 0xffff0000u) + e3 * __uint_as_float(p3.x & 0xffff0000u);
        a2 += e0 * __uint_as_float(p0.y << 16) + e1 * __uint_as_float(p1.y << 16)
            + e2 * __uint_as_float(p2.y << 16) + e3 * __uint_as_float(p3.y << 16);
        a3 += e0 * __uint_as_float(p0.y & 0xffff0000u) + e1 * __uint_as_float(p1.y & 0xffff0000u)
            + e2 * __uint_as_float(p2.y & 0xffff0000u) + e3 * __uint_as_float(p3.y & 0xffff0000u);
    }
    for (; i < end; i++) {
        int s0 = g_csr_src[i];
        float la = g_alS[s0 * 4 + hd] + adh;
        la = (la > 0.f) ? la : 0.2f * la;
        float e0 = __expf(la);
        den += e0;
        uint2 p0 = *(const uint2*)&g_hpb[(size_t)s0 * (Hq / 2) + lane * 2];
        a0 += e0 * __uint_as_float(p0.x << 16);
        a1 += e0 * __uint_as_float(p0.x & 0xffff0000u);
        a2 += e0 * __uint_as_float(p0.y << 16);
        a3 += e0 * __uint_as_float(p0.y & 0xffff0000u);
    }

    float dinv = 1.0f / (den + 1e-16f);
    a0 *= dinv; a1 *= dinv; a2 *= dinv; a3 *= dinv;

    size_t base = (size_t)n * Hq + lane * 4;
    float4 hv = *(const float4*)&g_h[base];
    float4 b4 = *(const float4*)&bg[lane * 4];
    float v0 = a0 + b4.x + hv.x;
    float v1 = a1 + b4.y + hv.y;
    float v2 = a2 + b4.z + hv.z;
    float v3 = a3 + b4.w + hv.w;

    float s = v0 + v1 + v2 + v3;
#pragma unroll
    for (int o = 16; o; o >>= 1) s += __shfl_xor_sync(0xffffffffu, s, o);
    float mu = s * (1.0f / 128.0f);
    float d0 = v0 - mu, d1 = v1 - mu, d2 = v2 - mu, d3 = v3 - mu;
    float q = d0 * d0 + d1 * d1 + d2 * d2 + d3 * d3;
#pragma unroll
    for (int o = 16; o; o >>= 1) q += __shfl_xor_sync(0xffffffffu, q, o);
    float rs = rsqrtf(q * (1.0f / 128.0f) + 1e-5f);

    float4 g4 = *(const float4*)&ga[lane * 4];
    float4 e4 = *(const float4*)&be[lane * 4];
    float4 outv;
    outv.x = d0 * rs * g4.x + e4.x;
    outv.y = d1 * rs * g4.y + e4.y;
    outv.z = d2 * rs * g4.z + e4.z;
    outv.w = d3 * rs * g4.w + e4.w;
    *(float4*)&g_h[base] = outv;
}

// ---------------- pooling ----------------
__global__ void pool_clear()
{
    int idx = blockIdx.x * blockDim.x + threadIdx.x;
    if (idx < Gq * Hq) { g_psum[idx] = 0.f; g_pmax[idx] = -INFINITY; }
    if (idx < Gq) g_gcnt[idx] = 0.f;
}

__global__ void pool_chunk(const int* __restrict__ n2g)
{
    __shared__ int sg[256];
    int d  = threadIdx.x;
    int n0 = blockIdx.x * 256;
    int n1 = n0 + 256; if (n1 > Nn) n1 = Nn;
    int cn = n1 - n0;
    for (int i = d; i < cn; i += 128) sg[i] = n2g[n0 + i];
    __syncthreads();

    int   curg = sg[0];
    float sum = 0.f, mx = -INFINITY;
    int   cnt = 0;
    for (int j = 0; j < cn; j++) {
        int g = sg[j];
        if (g != curg) {
            atomicAdd(&g_psum[curg * Hq + d], sum);
            atomicMaxFloat(&g_pmax[curg * Hq + d], mx);
            if (d == 0) atomicAdd(&g_gcnt[curg], (float)cnt);
            sum = 0.f; mx = -INFINITY; cnt = 0; curg = g;
        }
        float v = g_h[(size_t)(n0 + j) * Hq + d];
        sum += v; mx = fmaxf(mx, v); cnt++;
    }
    atomicAdd(&g_psum[curg * Hq + d], sum);
    atomicMaxFloat(&g_pmax[curg * Hq + d], mx);
    if (d == 0) atomicAdd(&g_gcnt[curg], (float)cnt);
}

// ---------------- final MLP head ----------------
__global__ void final_mlp(const float* __restrict__ Wq1, const float* __restrict__ bq1,
                          const float* __restrict__ gq, const float* __restrict__ beq,
                          const float* __restrict__ Wq2, const float* __restrict__ bq2,
                          float* __restrict__ out)
{
    int g = blockIdx.x;
    int tid = threadIdx.x;   // 256
    __shared__ float emb[2 * Hq];
    __shared__ float p[Hq];
    __shared__ float stats[2];

    if (tid < Hq) emb[tid] = g_psum[g * Hq + tid] / fmaxf(g_gcnt[g], 1.0f);
    else          emb[tid] = g_pmax[g * Hq + (tid - Hq)];
    __syncthreads();

    if (tid < Hq) {
        float t = bq1[tid];
        for (int k = 0; k < 2 * Hq; k++) t += emb[k] * Wq1[k * Hq + tid];
        p[tid] = t;
    }
    __syncthreads();

    if (tid == 0) {
        float s = 0.f;
        for (int j = 0; j < Hq; j++) s += p[j];
        float mu = s * (1.0f / 128.0f);
        float v = 0.f;
        for (int j = 0; j < Hq; j++) { float dd = p[j] - mu; v += dd * dd; }
        stats[0] = mu;
        stats[1] = rsqrtf(v * (1.0f / 128.0f) + 1e-5f);
    }
    __syncthreads();

    if (tid < Hq) {
        float y = (p[tid] - stats[0]) * stats[1] * gq[tid] + beq[tid];
        p[tid] = gelu_exact(y);
    }
    __syncthreads();

    float o = bq2[tid];
    for (int k = 0; k < Hq; k++) o += p[k] * Wq2[k * FOUTq + tid];
    out[g * FOUTq + tid] = o;
}

// ---------------- launch ----------------
extern "C" void kernel_launch(void* const* d_in, const int* in_sizes, int n_in,
                              void* d_out, int out_size)
{
    const float* x   = (const float*)d_in[0];
    const int*   ei  = (const int*)d_in[1];
    const int*   n2g = (const int*)d_in[2];
    const float* Wp  = (const float*)d_in[3];
    const float* bp  = (const float*)d_in[4];
    const float* Wq1 = (const float*)d_in[5];
    const float* bq1 = (const float*)d_in[6];
    const float* gq  = (const float*)d_in[7];
    const float* beq = (const float*)d_in[8];
    const float* Wq2 = (const float*)d_in[9];
    const float* bq2 = (const float*)d_in[10];
    float* out = (float*)d_out;

    float* ph = nullptr;
    void *pcnt = nullptr, *ptstat = nullptr;
    cudaGetSymbolAddress((void**)&ph, g_h);
    cudaGetSymbolAddress(&pcnt,  g_cnt_i);
    cudaGetSymbolAddress(&ptstat, g_tstat);

    static cudaStream_t s2 = nullptr;
    static cudaEvent_t evA = nullptr, evB = nullptr, evC = nullptr;
    if (s2 == nullptr) {
        cudaStreamCreateWithFlags(&s2, cudaStreamNonBlocking);
        cudaEventCreateWithFlags(&evA, cudaEventDisableTiming);
        cudaEventCreateWithFlags(&evB, cudaEventDisableTiming);
        cudaEventCreateWithFlags(&evC, cudaEventDisableTiming);
    }

    const int NB_GEMM = (Nn + 127) / 128;
    const int NB_E    = (ETOT + 255) / 256;
    const int NB_AGG  = (Nn + 7) / 8;
    const int NB_POOL = (Nn + 255) / 256;

    // ---- side stream: CSR build (memsets instead of clear kernels) ----
    cudaEventRecord(evA, 0);
    cudaStreamWaitEvent(s2, evA, 0);
    cudaMemsetAsync(pcnt, 0, Nn * sizeof(int), s2);
    cudaMemsetAsync(ptstat, 0, NTILE * sizeof(u64), s2);
    hist_dst<<<NB_E, 256, 0, s2>>>(ei);
    scan_dl<<<NTILE, 256, 0, s2>>>();
    csr_fill<<<NB_E, 256, 0, s2>>>(ei);
    cudaEventRecord(evB, s2);
    pool_clear<<<(Gq * Hq + 255) / 256, 256, 0, s2>>>();
    cudaEventRecord(evC, s2);

    // ---- main path ----
    gemm128T<DINq, true, false, false><<<NB_GEMM, 256>>>(x, Wp, bp, nullptr, nullptr, ph, Nn);

    gemm128T<Hq, false, true, true><<<NB_GEMM, 256>>>(
        ph, (const float*)d_in[11], nullptr,
        (const float*)d_in[12], (const float*)d_in[13], nullptr, Nn);

    cudaStreamWaitEvent(0, evB, 0);   // join: aggregation needs CSR

    gat_agg_ln<<<NB_AGG, 256>>>((const float*)d_in[14], (const float*)d_in[15],
                                (const float*)d_in[16]);

    gemm128T<Hq, false, true, true><<<NB_GEMM, 256>>>(
        ph, (const float*)d_in[17], nullptr,
        (const float*)d_in[18], (const float*)d_in[19], nullptr, Nn);
    gat_agg_ln<<<NB_AGG, 256>>>((const float*)d_in[20], (const float*)d_in[21],
                                (const float*)d_in[22]);

    cudaStreamWaitEvent(0, evC, 0);   // join: pooling needs pool_clear
    pool_chunk<<<NB_POOL, 128>>>(n2g);
    final_mlp<<<Gq, 256>>>(Wq1, bq1, gq, beq, Wq2, bq2, out);
}

// round 8
// speedup vs baseline: 1.3063x; 1.3063x over previous
#include <cuda_runtime.h>
#include <cuda_bf16.h>
#include <math.h>

#define Nn   100000
#define Ee   1600000
#define ETOT (Ee + Nn)
#define DINq 16
#define Hq   128
#define HEADSq 4
#define Gq   64
#define FOUTq 256
#define NTILE ((Nn + 255) / 256)

typedef unsigned long long u64;
typedef unsigned int u32;

// ---- scratch (static device memory) ----
__device__ float g_h[(size_t)Nn * Hq];
__device__ u32   g_hpb[(size_t)Nn * (Hq / 2)];
__device__ float g_alS[Nn * HEADSq];
__device__ float g_alD[Nn * HEADSq];
__device__ int   g_cnt_i[Nn];
__device__ int   g_rowptr[Nn + 1];
__device__ int   g_cursor[Nn];
__device__ int   g_csr_src[ETOT];
__device__ u64   g_tstat[NTILE];
__device__ float g_psum[Gq * Hq];
__device__ float g_pmax[Gq * Hq];
__device__ float g_gcnt[Gq];

#define FLAG_AGG (1ull << 62)
#define FLAG_INC (1ull << 63)

__device__ __forceinline__ void atomicMaxFloat(float* addr, float v) {
    if (v >= 0.0f) atomicMax((int*)addr, __float_as_int(v));
    else           atomicMin((unsigned int*)addr, __float_as_uint(v));
}

__device__ __forceinline__ float gelu_exact(float v) {
    return 0.5f * v * (1.0f + erff(v * 0.70710678118654752f));
}

__device__ __forceinline__ u32 bfpack(float lo, float hi) {
    u32 r; asm("cvt.rn.bf16x2.f32 %0, %1, %2;" : "=r"(r) : "f"(hi), "f"(lo)); return r;
}

__device__ __forceinline__ u32 tf32cvt(float f) {
    u32 r; asm("cvt.rna.tf32.f32 %0, %1;" : "=r"(r) : "f"(f)); return r;
}

__device__ __forceinline__ void mma_tf32(float* c, const u32* a, u32 b0, u32 b1) {
    asm volatile("mma.sync.aligned.m16n8k8.row.col.f32.tf32.tf32.f32 "
        "{%0,%1,%2,%3}, {%4,%5,%6,%7}, {%8,%9}, {%0,%1,%2,%3};"
        : "+f"(c[0]), "+f"(c[1]), "+f"(c[2]), "+f"(c[3])
        : "r"(a[0]), "r"(a[1]), "r"(a[2]), "r"(a[3]), "r"(b0), "r"(b1));
}

// ---- packed f32x2 helpers (proj GEMM only) ----
__device__ __forceinline__ void pfma(u64& d, u64 a, u64 b) {
    asm("fma.rn.f32x2 %0, %1, %2, %0;" : "+l"(d) : "l"(a), "l"(b));
}
__device__ __forceinline__ u64 pku(u32 lo, u32 hi) {
    u64 r; asm("mov.b64 %0, {%1,%2};" : "=l"(r) : "r"(lo), "r"(hi)); return r;
}
__device__ __forceinline__ u64 swap64(u64 p) { return pku((u32)(p >> 32), (u32)p); }
__device__ __forceinline__ float lo32(u64 p) { return __uint_as_float((u32)p); }
__device__ __forceinline__ float hi32(u64 p) { return __uint_as_float((u32)(p >> 32)); }

// ------- proj GEMM (K=16): h = gelu(x @ Wp + bp), FFMA2 -------
__global__ void gemm_proj(const float* __restrict__ A, const float* __restrict__ W,
                          const float* __restrict__ bias, float* __restrict__ C, int M)
{
    const int BN = 128, BK = 16;
    __shared__ float As[BK][BN + 4];
    __shared__ float Ws[BK][Hq + 4];
    int tid = threadIdx.x;
    int tx = tid & 15, ty = tid >> 4;
    int m0 = blockIdx.x * BN;
    int c0 = tx * 8;
    int r0 = ty * 8;

    u64 acc[4][4][2];
#pragma unroll
    for (int rp = 0; rp < 4; rp++)
#pragma unroll
        for (int cp = 0; cp < 4; cp++) { acc[rp][cp][0] = 0ull; acc[rp][cp][1] = 0ull; }

#pragma unroll
    for (int i = tid; i < BN * BK; i += 256) {
        int r = i >> 4, k = i & 15;
        As[k][r] = (m0 + r < M) ? A[(size_t)(m0 + r) * DINq + k] : 0.f;
    }
#pragma unroll
    for (int i = tid; i < BK * Hq; i += 256) {
        int k = i >> 7, c = i & 127;
        Ws[k][c] = W[(size_t)k * Hq + c];
    }
    __syncthreads();
#pragma unroll
    for (int kk = 0; kk < BK; kk++) {
        ulonglong2 ra = *(const ulonglong2*)&As[kk][r0];
        ulonglong2 rb = *(const ulonglong2*)&As[kk][r0 + 4];
        ulonglong2 wa = *(const ulonglong2*)&Ws[kk][c0];
        ulonglong2 wb = *(const ulonglong2*)&Ws[kk][c0 + 4];
        u64 rr[4] = {ra.x, ra.y, rb.x, rb.y};
        u64 cn[4] = {wa.x, wa.y, wb.x, wb.y};
        u64 cs[4] = {swap64(wa.x), swap64(wa.y), swap64(wb.x), swap64(wb.y)};
#pragma unroll
        for (int rp = 0; rp < 4; rp++)
#pragma unroll
            for (int cp = 0; cp < 4; cp++) {
                pfma(acc[rp][cp][0], rr[rp], cn[cp]);
                pfma(acc[rp][cp][1], rr[rp], cs[cp]);
            }
    }

    float v[8][8];
#pragma unroll
    for (int rp = 0; rp < 4; rp++)
#pragma unroll
        for (int cp = 0; cp < 4; cp++) {
            v[2 * rp][2 * cp]         = lo32(acc[rp][cp][0]);
            v[2 * rp + 1][2 * cp + 1] = hi32(acc[rp][cp][0]);
            v[2 * rp][2 * cp + 1]     = lo32(acc[rp][cp][1]);
            v[2 * rp + 1][2 * cp]     = hi32(acc[rp][cp][1]);
        }

    float b8[8];
#pragma unroll
    for (int q = 0; q < 8; q++) b8[q] = bias[c0 + q];
#pragma unroll
    for (int r = 0; r < 8; r++) {
        int m = m0 + r0 + r;
        if (m < M) {
#pragma unroll
            for (int q = 0; q < 8; q++) v[r][q] = gelu_exact(v[r][q] + b8[q]);
            float4 o0 = make_float4(v[r][0], v[r][1], v[r][2], v[r][3]);
            float4 o1 = make_float4(v[r][4], v[r][5], v[r][6], v[r][7]);
            *(float4*)&C[(size_t)m * Hq + c0] = o0;
            *(float4*)&C[(size_t)m * Hq + c0 + 4] = o1;
        }
    }
}

// ------- layer GEMM: tf32 tensor cores; bf16 hp out + fused attn logits -------
// C[M,128] = A[M,128] @ W[128,128]; 8 warps: warp (wr,wc) owns rows wr*32..+32, cols wc*64..+64
__global__ void gemm_tf32(const float* __restrict__ A, const float* __restrict__ W,
                          const float* __restrict__ a_s, const float* __restrict__ a_d, int M)
{
    __shared__ u32 Au[128][36];   // A chunk [128 rows][32 k], stride 36 (bank 4g+q: conflict-free)
    __shared__ u32 Wu[32][136];   // W chunk [32 k][128 n], stride 136 (bank 8q+g: conflict-free)
    int tid = threadIdx.x;
    int w = tid >> 5, lane = tid & 31;
    int wr = w >> 1, wc = w & 1;
    int q = lane & 3, g = lane >> 2;
    int m0 = blockIdx.x * 128;

    float c[2][8][4];
#pragma unroll
    for (int mt = 0; mt < 2; mt++)
#pragma unroll
        for (int nt = 0; nt < 8; nt++)
#pragma unroll
            for (int f = 0; f < 4; f++) c[mt][nt][f] = 0.f;

    for (int kc = 0; kc < 128; kc += 32) {
        // A chunk: 128 rows x 32 cols = 4096 floats; 256 thr x 4 x 4 iters
#pragma unroll
        for (int it = 0; it < 4; it++) {
            int idx = (it * 256 + tid) * 4;
            int r = idx >> 5, cI = idx & 31;
            float4 v4 = make_float4(0.f, 0.f, 0.f, 0.f);
            if (m0 + r < M) v4 = *(const float4*)&A[(size_t)(m0 + r) * Hq + kc + cI];
            Au[r][cI + 0] = tf32cvt(v4.x);
            Au[r][cI + 1] = tf32cvt(v4.y);
            Au[r][cI + 2] = tf32cvt(v4.z);
            Au[r][cI + 3] = tf32cvt(v4.w);
        }
        // W chunk: 32 k x 128 n = 4096 floats
#pragma unroll
        for (int it = 0; it < 4; it++) {
            int idx = (it * 256 + tid) * 4;
            int r = idx >> 7, cI = idx & 127;
            float4 v4 = *(const float4*)&W[(size_t)(kc + r) * Hq + cI];
            Wu[r][cI + 0] = tf32cvt(v4.x);
            Wu[r][cI + 1] = tf32cvt(v4.y);
            Wu[r][cI + 2] = tf32cvt(v4.z);
            Wu[r][cI + 3] = tf32cvt(v4.w);
        }
        __syncthreads();
#pragma unroll
        for (int kt = 0; kt < 32; kt += 8) {
            u32 af[2][4];
#pragma unroll
            for (int mt = 0; mt < 2; mt++) {
                int r = wr * 32 + mt * 16;
                af[mt][0] = Au[r + g][kt + q];
                af[mt][1] = Au[r + g + 8][kt + q];
                af[mt][2] = Au[r + g][kt + q + 4];
                af[mt][3] = Au[r + g + 8][kt + q + 4];
            }
#pragma unroll
            for (int nt = 0; nt < 8; nt++) {
                int n = wc * 64 + nt * 8 + g;
                u32 b0 = Wu[kt + q][n];
                u32 b1 = Wu[kt + q + 4][n];
                mma_tf32(c[0][nt], af[0], b0, b1);
                mma_tf32(c[1][nt], af[1], b0, b1);
            }
        }
        __syncthreads();
    }

    // ---- epilogue 1: bf16 pack of hp ----
#pragma unroll
    for (int mt = 0; mt < 2; mt++)
#pragma unroll
        for (int half = 0; half < 2; half++) {
            int m = m0 + wr * 32 + mt * 16 + g + half * 8;
            if (m < M) {
#pragma unroll
                for (int nt = 0; nt < 8; nt++) {
                    u32 pw = bfpack(c[mt][nt][2 * half], c[mt][nt][2 * half + 1]);
                    g_hpb[(size_t)m * (Hq / 2) + wc * 32 + nt * 4 + q] = pw;
                }
            }
        }

    // ---- epilogue 2: attn logits (2 heads per warp) ----
    float asv[8][2], adv[8][2];
#pragma unroll
    for (int nt = 0; nt < 8; nt++) {
        int col = wc * 64 + nt * 8 + 2 * q;
        asv[nt][0] = a_s[col];     asv[nt][1] = a_s[col + 1];
        adv[nt][0] = a_d[col];     adv[nt][1] = a_d[col + 1];
    }
#pragma unroll
    for (int mt = 0; mt < 2; mt++)
#pragma unroll
        for (int half = 0; half < 2; half++) {
            int m = m0 + wr * 32 + mt * 16 + g + half * 8;
            float ps0 = 0.f, ps1 = 0.f, pd0 = 0.f, pd1 = 0.f;
#pragma unroll
            for (int nt = 0; nt < 8; nt++) {
                float x0 = c[mt][nt][2 * half], x1 = c[mt][nt][2 * half + 1];
                float s = x0 * asv[nt][0] + x1 * asv[nt][1];
                float d = x0 * adv[nt][0] + x1 * adv[nt][1];
                if (nt < 4) { ps0 += s; pd0 += d; }
                else        { ps1 += s; pd1 += d; }
            }
            ps0 += __shfl_xor_sync(0xffffffffu, ps0, 1);
            ps1 += __shfl_xor_sync(0xffffffffu, ps1, 1);
            pd0 += __shfl_xor_sync(0xffffffffu, pd0, 1);
            pd1 += __shfl_xor_sync(0xffffffffu, pd1, 1);
            ps0 += __shfl_xor_sync(0xffffffffu, ps0, 2);
            ps1 += __shfl_xor_sync(0xffffffffu, ps1, 2);
            pd0 += __shfl_xor_sync(0xffffffffu, pd0, 2);
            pd1 += __shfl_xor_sync(0xffffffffu, pd1, 2);
            if (q == 0 && m < M) {
                int hb = wc * 2;
                g_alS[m * 4 + hb]     = ps0;
                g_alS[m * 4 + hb + 1] = ps1;
                g_alD[m * 4 + hb]     = pd0;
                g_alD[m * 4 + hb + 1] = pd1;
            }
        }
}

// ================= CSR build =================
__global__ void hist_dst(const int* __restrict__ ei)
{
    int e = blockIdx.x * blockDim.x + threadIdx.x;
    if (e < NTILE) g_tstat[e] = 0;      // zero lookback status for this replay
    if (e >= ETOT) return;
    int d = (e < Ee) ? ei[Ee + e] : (e - Ee);
    atomicAdd(&g_cnt_i[d], 1);
}

__global__ void scan_dl()
{
    __shared__ int s[256];
    __shared__ int s_prefix;
    int bid = blockIdx.x, tid = threadIdx.x;
    int i = bid * 256 + tid;
    int v = (i < Nn) ? g_cnt_i[i] : 0;
    s[tid] = v;
    __syncthreads();
#pragma unroll
    for (int o = 1; o < 256; o <<= 1) {
        int t = (tid >= o) ? s[tid - o] : 0;
        __syncthreads();
        s[tid] += t;
        __syncthreads();
    }
    int incl = s[tid];
    int agg  = s[255];

    if (tid == 0) {
        u64 pub = (bid == 0) ? (FLAG_INC | (u64)(u32)agg) : (FLAG_AGG | (u64)(u32)agg);
        atomicExch((unsigned long long*)&g_tstat[bid], pub);
        if (bid == 0) s_prefix = 0;
    }

    if (bid > 0 && tid < 32) {
        int lane = tid;
        u32 running = 0;
        int look = bid - 1;
        while (true) {
            int t = look - lane;
            u64 st;
            if (t >= 0) {
                do { st = *(volatile u64*)&g_tstat[t]; } while (st == 0);
            } else {
                st = FLAG_INC;
            }
            u32 incm = __ballot_sync(0xffffffffu, (st & FLAG_INC) != 0);
            u32 val;
            if (incm) {
                int L = __ffs(incm) - 1;
                val = (lane <= L) ? (u32)st : 0;
            } else {
                val = (u32)st;
            }
#pragma unroll
            for (int o = 16; o; o >>= 1) val += __shfl_xor_sync(0xffffffffu, val, o);
            running += val;
            if (incm) break;
            look -= 32;
        }
        if (lane == 0) {
            atomicExch((unsigned long long*)&g_tstat[bid],
                       FLAG_INC | (u64)(u32)(running + (u32)agg));
            s_prefix = (int)running;
        }
    }
    __syncthreads();

    int pre = s_prefix;
    if (i < Nn) {
        int r = pre + incl - v;
        g_rowptr[i] = r;
        g_cursor[i] = r;
    }
    if (i == 0) g_rowptr[Nn] = ETOT;
}

__global__ void csr_fill(const int* __restrict__ ei)
{
    int e = blockIdx.x * blockDim.x + threadIdx.x;
    if (e >= ETOT) return;
    int s, d;
    if (e < Ee) { s = ei[e]; d = ei[Ee + e]; } else { s = d = e - Ee; }
    int pos = atomicAdd(&g_cursor[d], 1);
    g_csr_src[pos] = s;
}

// == single-pass GAT aggregation + bias + residual + LayerNorm (warp per node) ==
__global__ void gat_agg_ln(const float* __restrict__ bg, const float* __restrict__ ga,
                           const float* __restrict__ be)
{
    int n = blockIdx.x * 8 + (threadIdx.x >> 5);
    if (n >= Nn) return;
    int lane = threadIdx.x & 31;
    int hd = lane >> 3;
    int start = g_rowptr[n];
    int end   = g_rowptr[n + 1];

    float adh = g_alD[n * 4 + hd];

    float a0 = 0.f, a1 = 0.f, a2 = 0.f, a3 = 0.f, den = 0.f;
    int i = start;
    for (; i + 1 < end; i += 2) {
        int s0 = g_csr_src[i];
        int s1 = g_csr_src[i + 1];
        float la = g_alS[s0 * 4 + hd] + adh;
        float lb = g_alS[s1 * 4 + hd] + adh;
        la = (la > 0.f) ? la : 0.2f * la;
        lb = (lb > 0.f) ? lb : 0.2f * lb;
        float e0 = __expf(la);
        float e1 = __expf(lb);
        den += e0 + e1;
        uint2 p0 = *(const uint2*)&g_hpb[(size_t)s0 * (Hq / 2) + lane * 2];
        uint2 p1 = *(const uint2*)&g_hpb[(size_t)s1 * (Hq / 2) + lane * 2];
        a0 += e0 * __uint_as_float(p0.x << 16) + e1 * __uint_as_float(p1.x << 16);
        a1 += e0 * __uint_as_float(p0.x & 0xffff0000u) + e1 * __uint_as_float(p1.x & 0xffff0000u);
        a2 += e0 * __uint_as_float(p0.y << 16) + e1 * __uint_as_float(p1.y << 16);
        a3 += e0 * __uint_as_float(p0.y & 0xffff0000u) + e1 * __uint_as_float(p1.y & 0xffff0000u);
    }
    if (i < end) {
        int s0 = g_csr_src[i];
        float la = g_alS[s0 * 4 + hd] + adh;
        la = (la > 0.f) ? la : 0.2f * la;
        float e0 = __expf(la);
        den += e0;
        uint2 p0 = *(const uint2*)&g_hpb[(size_t)s0 * (Hq / 2) + lane * 2];
        a0 += e0 * __uint_as_float(p0.x << 16);
        a1 += e0 * __uint_as_float(p0.x & 0xffff0000u);
        a2 += e0 * __uint_as_float(p0.y << 16);
        a3 += e0 * __uint_as_float(p0.y & 0xffff0000u);
    }

    float dinv = 1.0f / (den + 1e-16f);
    a0 *= dinv; a1 *= dinv; a2 *= dinv; a3 *= dinv;

    size_t base = (size_t)n * Hq + lane * 4;
    float4 hv = *(const float4*)&g_h[base];
    float4 b4 = *(const float4*)&bg[lane * 4];
    float v0 = a0 + b4.x + hv.x;
    float v1 = a1 + b4.y + hv.y;
    float v2 = a2 + b4.z + hv.z;
    float v3 = a3 + b4.w + hv.w;

    float s = v0 + v1 + v2 + v3;
#pragma unroll
    for (int o = 16; o; o >>= 1) s += __shfl_xor_sync(0xffffffffu, s, o);
    float mu = s * (1.0f / 128.0f);
    float d0 = v0 - mu, d1 = v1 - mu, d2 = v2 - mu, d3 = v3 - mu;
    float qv = d0 * d0 + d1 * d1 + d2 * d2 + d3 * d3;
#pragma unroll
    for (int o = 16; o; o >>= 1) qv += __shfl_xor_sync(0xffffffffu, qv, o);
    float rs = rsqrtf(qv * (1.0f / 128.0f) + 1e-5f);

    float4 g4 = *(const float4*)&ga[lane * 4];
    float4 e4 = *(const float4*)&be[lane * 4];
    float4 outv;
    outv.x = d0 * rs * g4.x + e4.x;
    outv.y = d1 * rs * g4.y + e4.y;
    outv.z = d2 * rs * g4.z + e4.z;
    outv.w = d3 * rs * g4.w + e4.w;
    *(float4*)&g_h[base] = outv;
}

// ---------------- pooling ----------------
__global__ void pool_clear()
{
    int idx = blockIdx.x * blockDim.x + threadIdx.x;
    if (idx < Gq * Hq) { g_psum[idx] = 0.f; g_pmax[idx] = -INFINITY; }
    if (idx < Gq) g_gcnt[idx] = 0.f;
}

__global__ void pool_chunk(const int* __restrict__ n2g)
{
    __shared__ int sg[256];
    int d  = threadIdx.x;
    int n0 = blockIdx.x * 256;
    int n1 = n0 + 256; if (n1 > Nn) n1 = Nn;
    int cn = n1 - n0;
    for (int i = d; i < cn; i += 128) sg[i] = n2g[n0 + i];
    __syncthreads();

    int   curg = sg[0];
    float sum = 0.f, mx = -INFINITY;
    int   cnt = 0;
    for (int j = 0; j < cn; j++) {
        int g = sg[j];
        if (g != curg) {
            atomicAdd(&g_psum[curg * Hq + d], sum);
            atomicMaxFloat(&g_pmax[curg * Hq + d], mx);
            if (d == 0) atomicAdd(&g_gcnt[curg], (float)cnt);
            sum = 0.f; mx = -INFINITY; cnt = 0; curg = g;
        }
        float v = g_h[(size_t)(n0 + j) * Hq + d];
        sum += v; mx = fmaxf(mx, v); cnt++;
    }
    atomicAdd(&g_psum[curg * Hq + d], sum);
    atomicMaxFloat(&g_pmax[curg * Hq + d], mx);
    if (d == 0) atomicAdd(&g_gcnt[curg], (float)cnt);
}

// ---------------- final MLP head ----------------
__global__ void final_mlp(const float* __restrict__ Wq1, const float* __restrict__ bq1,
                          const float* __restrict__ gq, const float* __restrict__ beq,
                          const float* __restrict__ Wq2, const float* __restrict__ bq2,
                          float* __restrict__ out)
{
    int g = blockIdx.x;
    int tid = threadIdx.x;   // 256
    __shared__ float emb[2 * Hq];
    __shared__ float p[Hq];
    __shared__ float stats[2];

    if (tid < Hq) emb[tid] = g_psum[g * Hq + tid] / fmaxf(g_gcnt[g], 1.0f);
    else          emb[tid] = g_pmax[g * Hq + (tid - Hq)];
    __syncthreads();

    if (tid < Hq) {
        float t = bq1[tid];
        for (int k = 0; k < 2 * Hq; k++) t += emb[k] * Wq1[k * Hq + tid];
        p[tid] = t;
    }
    __syncthreads();

    if (tid == 0) {
        float s = 0.f;
        for (int j = 0; j < Hq; j++) s += p[j];
        float mu = s * (1.0f / 128.0f);
        float v = 0.f;
        for (int j = 0; j < Hq; j++) { float dd = p[j] - mu; v += dd * dd; }
        stats[0] = mu;
        stats[1] = rsqrtf(v * (1.0f / 128.0f) + 1e-5f);
    }
    __syncthreads();

    if (tid < Hq) {
        float y = (p[tid] - stats[0]) * stats[1] * gq[tid] + beq[tid];
        p[tid] = gelu_exact(y);
    }
    __syncthreads();

    float o = bq2[tid];
    for (int k = 0; k < Hq; k++) o += p[k] * Wq2[k * FOUTq + tid];
    out[g * FOUTq + tid] = o;
}

// ---------------- launch ----------------
extern "C" void kernel_launch(void* const* d_in, const int* in_sizes, int n_in,
                              void* d_out, int out_size)
{
    const float* x   = (const float*)d_in[0];
    const int*   ei  = (const int*)d_in[1];
    const int*   n2g = (const int*)d_in[2];
    const float* Wp  = (const float*)d_in[3];
    const float* bp  = (const float*)d_in[4];
    const float* Wq1 = (const float*)d_in[5];
    const float* bq1 = (const float*)d_in[6];
    const float* gq  = (const float*)d_in[7];
    const float* beq = (const float*)d_in[8];
    const float* Wq2 = (const float*)d_in[9];
    const float* bq2 = (const float*)d_in[10];
    float* out = (float*)d_out;

    float* ph = nullptr;
    void* pcnt = nullptr;
    cudaGetSymbolAddress((void**)&ph, g_h);
    cudaGetSymbolAddress(&pcnt, g_cnt_i);

    static cudaStream_t s2 = nullptr;
    static cudaEvent_t evA = nullptr, evB = nullptr, evC = nullptr;
    if (s2 == nullptr) {
        cudaStreamCreateWithFlags(&s2, cudaStreamNonBlocking);
        cudaEventCreateWithFlags(&evA, cudaEventDisableTiming);
        cudaEventCreateWithFlags(&evB, cudaEventDisableTiming);
        cudaEventCreateWithFlags(&evC, cudaEventDisableTiming);
    }

    const int NB_GEMM = (Nn + 127) / 128;
    const int NB_E    = (ETOT + 255) / 256;
    const int NB_AGG  = (Nn + 7) / 8;
    const int NB_POOL = (Nn + 255) / 256;

    // ---- side stream: CSR build ----
    cudaEventRecord(evA, 0);
    cudaStreamWaitEvent(s2, evA, 0);
    cudaMemsetAsync(pcnt, 0, Nn * sizeof(int), s2);        // launch 0
    hist_dst<<<NB_E, 256, 0, s2>>>(ei);                    // launch 1 (also zeroes g_tstat)
    scan_dl<<<NTILE, 256, 0, s2>>>();                      // launch 2
    csr_fill<<<NB_E, 256, 0, s2>>>(ei);                    // launch 3
    cudaEventRecord(evB, s2);

    // ---- main path ----
    gemm_proj<<<NB_GEMM, 256>>>(x, Wp, bp, ph, Nn);        // launch 4
    gemm_tf32<<<NB_GEMM, 256>>>(ph, (const float*)d_in[11],
                                (const float*)d_in[12], (const float*)d_in[13], Nn);  // launch 5 (ncu)

    cudaStreamWaitEvent(0, evB, 0);
    gat_agg_ln<<<NB_AGG, 256>>>((const float*)d_in[14], (const float*)d_in[15],
                                (const float*)d_in[16]);

    pool_clear<<<(Gq * Hq + 255) / 256, 256, 0, s2>>>();   // overlapped on side stream
    cudaEventRecord(evC, s2);

    gemm_tf32<<<NB_GEMM, 256>>>(ph, (const float*)d_in[17],
                                (const float*)d_in[18], (const float*)d_in[19], Nn);
    gat_agg_ln<<<NB_AGG, 256>>>((const float*)d_in[20], (const float*)d_in[21],
                                (const float*)d_in[22]);

    cudaStreamWaitEvent(0, evC, 0);
    pool_chunk<<<NB_POOL, 128>>>(n2g);
    final_mlp<<<Gq, 256>>>(Wq1, bq1, gq, beq, Wq2, bq2, out);
}

// round 9
// speedup vs baseline: 1.3147x; 1.0064x over previous
#include <cuda_runtime.h>
#include <cuda_bf16.h>
#include <math.h>

#define Nn   100000
#define Ee   1600000
#define ETOT (Ee + Nn)
#define DINq 16
#define Hq   128
#define HEADSq 4
#define Gq   64
#define FOUTq 256
#define NTILE ((Nn + 255) / 256)

typedef unsigned long long u64;
typedef unsigned int u32;

// ---- scratch (static device memory) ----
__device__ float g_h[(size_t)Nn * Hq];
__device__ u32   g_hpb[(size_t)Nn * (Hq / 2)];
__device__ float g_alS[Nn * HEADSq];
__device__ float g_alD[Nn * HEADSq];
__device__ int   g_cnt_i[Nn];
__device__ int   g_rowptr[Nn + 1];
__device__ int   g_cursor[Nn];
__device__ int   g_csr_src[ETOT];
__device__ u64   g_tstat[NTILE];
__device__ float g_psum[Gq * Hq];
__device__ float g_pmax[Gq * Hq];
__device__ float g_gcnt[Gq];

#define FLAG_AGG (1ull << 62)
#define FLAG_INC (1ull << 63)

__device__ __forceinline__ void atomicMaxFloat(float* addr, float v) {
    if (v >= 0.0f) atomicMax((int*)addr, __float_as_int(v));
    else           atomicMin((unsigned int*)addr, __float_as_uint(v));
}

__device__ __forceinline__ float gelu_exact(float v) {
    return 0.5f * v * (1.0f + erff(v * 0.70710678118654752f));
}

__device__ __forceinline__ u32 bfpack(float lo, float hi) {
    u32 r; asm("cvt.rn.bf16x2.f32 %0, %1, %2;" : "=r"(r) : "f"(hi), "f"(lo)); return r;
}

__device__ __forceinline__ u32 tf32cvt(float f) {
    u32 r; asm("cvt.rna.tf32.f32 %0, %1;" : "=r"(r) : "f"(f)); return r;
}

__device__ __forceinline__ void mma_tf32(float* c, const u32* a, u32 b0, u32 b1) {
    asm volatile("mma.sync.aligned.m16n8k8.row.col.f32.tf32.tf32.f32 "
        "{%0,%1,%2,%3}, {%4,%5,%6,%7}, {%8,%9}, {%0,%1,%2,%3};"
        : "+f"(c[0]), "+f"(c[1]), "+f"(c[2]), "+f"(c[3])
        : "r"(a[0]), "r"(a[1]), "r"(a[2]), "r"(a[3]), "r"(b0), "r"(b1));
}

// ---- packed f32x2 helpers (proj GEMM only) ----
__device__ __forceinline__ void pfma(u64& d, u64 a, u64 b) {
    asm("fma.rn.f32x2 %0, %1, %2, %0;" : "+l"(d) : "l"(a), "l"(b));
}
__device__ __forceinline__ u64 pku(u32 lo, u32 hi) {
    u64 r; asm("mov.b64 %0, {%1,%2};" : "=l"(r) : "r"(lo), "r"(hi)); return r;
}
__device__ __forceinline__ u64 swap64(u64 p) { return pku((u32)(p >> 32), (u32)p); }
__device__ __forceinline__ float lo32(u64 p) { return __uint_as_float((u32)p); }
__device__ __forceinline__ float hi32(u64 p) { return __uint_as_float((u32)(p >> 32)); }

// ------- proj GEMM (K=16): h = gelu(x @ Wp + bp), FFMA2 -------
__global__ void gemm_proj(const float* __restrict__ A, const float* __restrict__ W,
                          const float* __restrict__ bias, float* __restrict__ C, int M)
{
    const int BN = 128, BK = 16;
    __shared__ float As[BK][BN + 4];
    __shared__ float Ws[BK][Hq + 4];
    int tid = threadIdx.x;
    int tx = tid & 15, ty = tid >> 4;
    int m0 = blockIdx.x * BN;
    int c0 = tx * 8;
    int r0 = ty * 8;

    u64 acc[4][4][2];
#pragma unroll
    for (int rp = 0; rp < 4; rp++)
#pragma unroll
        for (int cp = 0; cp < 4; cp++) { acc[rp][cp][0] = 0ull; acc[rp][cp][1] = 0ull; }

#pragma unroll
    for (int i = tid; i < BN * BK; i += 256) {
        int r = i >> 4, k = i & 15;
        As[k][r] = (m0 + r < M) ? A[(size_t)(m0 + r) * DINq + k] : 0.f;
    }
#pragma unroll
    for (int i = tid; i < BK * Hq; i += 256) {
        int k = i >> 7, c = i & 127;
        Ws[k][c] = W[(size_t)k * Hq + c];
    }
    __syncthreads();
#pragma unroll
    for (int kk = 0; kk < BK; kk++) {
        ulonglong2 ra = *(const ulonglong2*)&As[kk][r0];
        ulonglong2 rb = *(const ulonglong2*)&As[kk][r0 + 4];
        ulonglong2 wa = *(const ulonglong2*)&Ws[kk][c0];
        ulonglong2 wb = *(const ulonglong2*)&Ws[kk][c0 + 4];
        u64 rr[4] = {ra.x, ra.y, rb.x, rb.y};
        u64 cn[4] = {wa.x, wa.y, wb.x, wb.y};
        u64 cs[4] = {swap64(wa.x), swap64(wa.y), swap64(wb.x), swap64(wb.y)};
#pragma unroll
        for (int rp = 0; rp < 4; rp++)
#pragma unroll
            for (int cp = 0; cp < 4; cp++) {
                pfma(acc[rp][cp][0], rr[rp], cn[cp]);
                pfma(acc[rp][cp][1], rr[rp], cs[cp]);
            }
    }

    float v[8][8];
#pragma unroll
    for (int rp = 0; rp < 4; rp++)
#pragma unroll
        for (int cp = 0; cp < 4; cp++) {
            v[2 * rp][2 * cp]         = lo32(acc[rp][cp][0]);
            v[2 * rp + 1][2 * cp + 1] = hi32(acc[rp][cp][0]);
            v[2 * rp][2 * cp + 1]     = lo32(acc[rp][cp][1]);
            v[2 * rp + 1][2 * cp]     = hi32(acc[rp][cp][1]);
        }

    float b8[8];
#pragma unroll
    for (int q = 0; q < 8; q++) b8[q] = bias[c0 + q];
#pragma unroll
    for (int r = 0; r < 8; r++) {
        int m = m0 + r0 + r;
        if (m < M) {
#pragma unroll
            for (int q = 0; q < 8; q++) v[r][q] = gelu_exact(v[r][q] + b8[q]);
            float4 o0 = make_float4(v[r][0], v[r][1], v[r][2], v[r][3]);
            float4 o1 = make_float4(v[r][4], v[r][5], v[r][6], v[r][7]);
            *(float4*)&C[(size_t)m * Hq + c0] = o0;
            *(float4*)&C[(size_t)m * Hq + c0 + 4] = o1;
        }
    }
}

// ------- layer GEMM: tf32 tensor cores; bf16 hp out + fused attn logits -------
__global__ void gemm_tf32(const float* __restrict__ A, const float* __restrict__ W,
                          const float* __restrict__ a_s, const float* __restrict__ a_d, int M)
{
    __shared__ u32 Au[128][36];
    __shared__ u32 Wu[32][136];
    int tid = threadIdx.x;
    int w = tid >> 5, lane = tid & 31;
    int wr = w >> 1, wc = w & 1;
    int q = lane & 3, g = lane >> 2;
    int m0 = blockIdx.x * 128;

    float c[2][8][4];
#pragma unroll
    for (int mt = 0; mt < 2; mt++)
#pragma unroll
        for (int nt = 0; nt < 8; nt++)
#pragma unroll
            for (int f = 0; f < 4; f++) c[mt][nt][f] = 0.f;

    for (int kc = 0; kc < 128; kc += 32) {
#pragma unroll
        for (int it = 0; it < 4; it++) {
            int idx = (it * 256 + tid) * 4;
            int r = idx >> 5, cI = idx & 31;
            float4 v4 = make_float4(0.f, 0.f, 0.f, 0.f);
            if (m0 + r < M) v4 = *(const float4*)&A[(size_t)(m0 + r) * Hq + kc + cI];
            Au[r][cI + 0] = tf32cvt(v4.x);
            Au[r][cI + 1] = tf32cvt(v4.y);
            Au[r][cI + 2] = tf32cvt(v4.z);
            Au[r][cI + 3] = tf32cvt(v4.w);
        }
#pragma unroll
        for (int it = 0; it < 4; it++) {
            int idx = (it * 256 + tid) * 4;
            int r = idx >> 7, cI = idx & 127;
            float4 v4 = *(const float4*)&W[(size_t)(kc + r) * Hq + cI];
            Wu[r][cI + 0] = tf32cvt(v4.x);
            Wu[r][cI + 1] = tf32cvt(v4.y);
            Wu[r][cI + 2] = tf32cvt(v4.z);
            Wu[r][cI + 3] = tf32cvt(v4.w);
        }
        __syncthreads();
#pragma unroll
        for (int kt = 0; kt < 32; kt += 8) {
            u32 af[2][4];
#pragma unroll
            for (int mt = 0; mt < 2; mt++) {
                int r = wr * 32 + mt * 16;
                af[mt][0] = Au[r + g][kt + q];
                af[mt][1] = Au[r + g + 8][kt + q];
                af[mt][2] = Au[r + g][kt + q + 4];
                af[mt][3] = Au[r + g + 8][kt + q + 4];
            }
#pragma unroll
            for (int nt = 0; nt < 8; nt++) {
                int n = wc * 64 + nt * 8 + g;
                u32 b0 = Wu[kt + q][n];
                u32 b1 = Wu[kt + q + 4][n];
                mma_tf32(c[0][nt], af[0], b0, b1);
                mma_tf32(c[1][nt], af[1], b0, b1);
            }
        }
        __syncthreads();
    }

#pragma unroll
    for (int mt = 0; mt < 2; mt++)
#pragma unroll
        for (int half = 0; half < 2; half++) {
            int m = m0 + wr * 32 + mt * 16 + g + half * 8;
            if (m < M) {
#pragma unroll
                for (int nt = 0; nt < 8; nt++) {
                    u32 pw = bfpack(c[mt][nt][2 * half], c[mt][nt][2 * half + 1]);
                    g_hpb[(size_t)m * (Hq / 2) + wc * 32 + nt * 4 + q] = pw;
                }
            }
        }

    float asv[8][2], adv[8][2];
#pragma unroll
    for (int nt = 0; nt < 8; nt++) {
        int col = wc * 64 + nt * 8 + 2 * q;
        asv[nt][0] = a_s[col];     asv[nt][1] = a_s[col + 1];
        adv[nt][0] = a_d[col];     adv[nt][1] = a_d[col + 1];
    }
#pragma unroll
    for (int mt = 0; mt < 2; mt++)
#pragma unroll
        for (int half = 0; half < 2; half++) {
            int m = m0 + wr * 32 + mt * 16 + g + half * 8;
            float ps0 = 0.f, ps1 = 0.f, pd0 = 0.f, pd1 = 0.f;
#pragma unroll
            for (int nt = 0; nt < 8; nt++) {
                float x0 = c[mt][nt][2 * half], x1 = c[mt][nt][2 * half + 1];
                float s = x0 * asv[nt][0] + x1 * asv[nt][1];
                float d = x0 * adv[nt][0] + x1 * adv[nt][1];
                if (nt < 4) { ps0 += s; pd0 += d; }
                else        { ps1 += s; pd1 += d; }
            }
            ps0 += __shfl_xor_sync(0xffffffffu, ps0, 1);
            ps1 += __shfl_xor_sync(0xffffffffu, ps1, 1);
            pd0 += __shfl_xor_sync(0xffffffffu, pd0, 1);
            pd1 += __shfl_xor_sync(0xffffffffu, pd1, 1);
            ps0 += __shfl_xor_sync(0xffffffffu, ps0, 2);
            ps1 += __shfl_xor_sync(0xffffffffu, ps1, 2);
            pd0 += __shfl_xor_sync(0xffffffffu, pd0, 2);
            pd1 += __shfl_xor_sync(0xffffffffu, pd1, 2);
            if (q == 0 && m < M) {
                int hb = wc * 2;
                g_alS[m * 4 + hb]     = ps0;
                g_alS[m * 4 + hb + 1] = ps1;
                g_alD[m * 4 + hb]     = pd0;
                g_alD[m * 4 + hb + 1] = pd1;
            }
        }
}

// ================= CSR build =================
__global__ void hist_dst(const int* __restrict__ ei)
{
    int e = blockIdx.x * blockDim.x + threadIdx.x;
    if (e < NTILE) g_tstat[e] = 0;
    if (e >= ETOT) return;
    int d = (e < Ee) ? ei[Ee + e] : (e - Ee);
    atomicAdd(&g_cnt_i[d], 1);
}

__global__ void scan_dl()
{
    __shared__ int s[256];
    __shared__ int s_prefix;
    int bid = blockIdx.x, tid = threadIdx.x;
    int i = bid * 256 + tid;
    int v = (i < Nn) ? g_cnt_i[i] : 0;
    s[tid] = v;
    __syncthreads();
#pragma unroll
    for (int o = 1; o < 256; o <<= 1) {
        int t = (tid >= o) ? s[tid - o] : 0;
        __syncthreads();
        s[tid] += t;
        __syncthreads();
    }
    int incl = s[tid];
    int agg  = s[255];

    if (tid == 0) {
        u64 pub = (bid == 0) ? (FLAG_INC | (u64)(u32)agg) : (FLAG_AGG | (u64)(u32)agg);
        atomicExch((unsigned long long*)&g_tstat[bid], pub);
        if (bid == 0) s_prefix = 0;
    }

    if (bid > 0 && tid < 32) {
        int lane = tid;
        u32 running = 0;
        int look = bid - 1;
        while (true) {
            int t = look - lane;
            u64 st;
            if (t >= 0) {
                do { st = *(volatile u64*)&g_tstat[t]; } while (st == 0);
            } else {
                st = FLAG_INC;
            }
            u32 incm = __ballot_sync(0xffffffffu, (st & FLAG_INC) != 0);
            u32 val;
            if (incm) {
                int L = __ffs(incm) - 1;
                val = (lane <= L) ? (u32)st : 0;
            } else {
                val = (u32)st;
            }
#pragma unroll
            for (int o = 16; o; o >>= 1) val += __shfl_xor_sync(0xffffffffu, val, o);
            running += val;
            if (incm) break;
            look -= 32;
        }
        if (lane == 0) {
            atomicExch((unsigned long long*)&g_tstat[bid],
                       FLAG_INC | (u64)(u32)(running + (u32)agg));
            s_prefix = (int)running;
        }
    }
    __syncthreads();

    int pre = s_prefix;
    if (i < Nn) {
        int r = pre + incl - v;
        g_rowptr[i] = r;
        g_cursor[i] = r;
    }
    if (i == 0) g_rowptr[Nn] = ETOT;
}

__global__ void csr_fill(const int* __restrict__ ei)
{
    int e = blockIdx.x * blockDim.x + threadIdx.x;
    if (e >= ETOT) return;
    int s, d;
    if (e < Ee) { s = ei[e]; d = ei[Ee + e]; } else { s = d = e - Ee; }
    int pos = atomicAdd(&g_cursor[d], 1);
    g_csr_src[pos] = s;
}

// == single-pass GAT aggregation, unroll-8 batched loads, + bias/residual/LN ==
__global__ void gat_agg_ln(const float* __restrict__ bg, const float* __restrict__ ga,
                           const float* __restrict__ be)
{
    int n = blockIdx.x * 8 + (threadIdx.x >> 5);
    if (n >= Nn) return;
    int lane = threadIdx.x & 31;
    int hd = lane >> 3;
    int start = g_rowptr[n];
    int end   = g_rowptr[n + 1];

    float adh = g_alD[n * 4 + hd];

    float a0 = 0.f, a1 = 0.f, a2 = 0.f, a3 = 0.f, den = 0.f;
    int i = start;
    for (; i + 8 <= end; i += 8) {
        int s[8];
#pragma unroll
        for (int j = 0; j < 8; j++) s[j] = g_csr_src[i + j];
        float e[8];
#pragma unroll
        for (int j = 0; j < 8; j++) {
            float l = g_alS[s[j] * 4 + hd] + adh;
            l = (l > 0.f) ? l : 0.2f * l;
            e[j] = __expf(l);
        }
        uint2 p[8];
#pragma unroll
        for (int j = 0; j < 8; j++)
            p[j] = *(const uint2*)&g_hpb[(size_t)s[j] * (Hq / 2) + lane * 2];
#pragma unroll
        for (int j = 0; j < 8; j++) {
            den += e[j];
            a0 += e[j] * __uint_as_float(p[j].x << 16);
            a1 += e[j] * __uint_as_float(p[j].x & 0xffff0000u);
            a2 += e[j] * __uint_as_float(p[j].y << 16);
            a3 += e[j] * __uint_as_float(p[j].y & 0xffff0000u);
        }
    }
    {
        int rem = end - i;
        int s[8];
#pragma unroll
        for (int j = 0; j < 8; j++) s[j] = (j < rem) ? g_csr_src[i + j] : -1;
#pragma unroll
        for (int j = 0; j < 8; j++) {
            if (j < rem) {
                float l = g_alS[s[j] * 4 + hd] + adh;
                l = (l > 0.f) ? l : 0.2f * l;
                float ej = __expf(l);
                uint2 pj = *(const uint2*)&g_hpb[(size_t)s[j] * (Hq / 2) + lane * 2];
                den += ej;
                a0 += ej * __uint_as_float(pj.x << 16);
                a1 += ej * __uint_as_float(pj.x & 0xffff0000u);
                a2 += ej * __uint_as_float(pj.y << 16);
                a3 += ej * __uint_as_float(pj.y & 0xffff0000u);
            }
        }
    }

    float dinv = 1.0f / (den + 1e-16f);
    a0 *= dinv; a1 *= dinv; a2 *= dinv; a3 *= dinv;

    size_t base = (size_t)n * Hq + lane * 4;
    float4 hv = *(const float4*)&g_h[base];
    float4 b4 = *(const float4*)&bg[lane * 4];
    float v0 = a0 + b4.x + hv.x;
    float v1 = a1 + b4.y + hv.y;
    float v2 = a2 + b4.z + hv.z;
    float v3 = a3 + b4.w + hv.w;

    float s = v0 + v1 + v2 + v3;
#pragma unroll
    for (int o = 16; o; o >>= 1) s += __shfl_xor_sync(0xffffffffu, s, o);
    float mu = s * (1.0f / 128.0f);
    float d0 = v0 - mu, d1 = v1 - mu, d2 = v2 - mu, d3 = v3 - mu;
    float qv = d0 * d0 + d1 * d1 + d2 * d2 + d3 * d3;
#pragma unroll
    for (int o = 16; o; o >>= 1) qv += __shfl_xor_sync(0xffffffffu, qv, o);
    float rs = rsqrtf(qv * (1.0f / 128.0f) + 1e-5f);

    float4 g4 = *(const float4*)&ga[lane * 4];
    float4 e4 = *(const float4*)&be[lane * 4];
    float4 outv;
    outv.x = d0 * rs * g4.x + e4.x;
    outv.y = d1 * rs * g4.y + e4.y;
    outv.z = d2 * rs * g4.z + e4.z;
    outv.w = d3 * rs * g4.w + e4.w;
    *(float4*)&g_h[base] = outv;
}

// ---------------- pooling ----------------
__global__ void pool_clear()
{
    int idx = blockIdx.x * blockDim.x + threadIdx.x;
    if (idx < Gq * Hq) { g_psum[idx] = 0.f; g_pmax[idx] = -INFINITY; }
    if (idx < Gq) g_gcnt[idx] = 0.f;
}

__global__ void pool_chunk(const int* __restrict__ n2g)
{
    __shared__ int sg[256];
    int d  = threadIdx.x;
    int n0 = blockIdx.x * 256;
    int n1 = n0 + 256; if (n1 > Nn) n1 = Nn;
    int cn = n1 - n0;
    for (int i = d; i < cn; i += 128) sg[i] = n2g[n0 + i];
    __syncthreads();

    int   curg = sg[0];
    float sum = 0.f, mx = -INFINITY;
    int   cnt = 0;
    for (int j = 0; j < cn; j++) {
        int g = sg[j];
        if (g != curg) {
            atomicAdd(&g_psum[curg * Hq + d], sum);
            atomicMaxFloat(&g_pmax[curg * Hq + d], mx);
            if (d == 0) atomicAdd(&g_gcnt[curg], (float)cnt);
            sum = 0.f; mx = -INFINITY; cnt = 0; curg = g;
        }
        float v = g_h[(size_t)(n0 + j) * Hq + d];
        sum += v; mx = fmaxf(mx, v); cnt++;
    }
    atomicAdd(&g_psum[curg * Hq + d], sum);
    atomicMaxFloat(&g_pmax[curg * Hq + d], mx);
    if (d == 0) atomicAdd(&g_gcnt[curg], (float)cnt);
}

// ---------------- final MLP head ----------------
__global__ void final_mlp(const float* __restrict__ Wq1, const float* __restrict__ bq1,
                          const float* __restrict__ gq, const float* __restrict__ beq,
                          const float* __restrict__ Wq2, const float* __restrict__ bq2,
                          float* __restrict__ out)
{
    int g = blockIdx.x;
    int tid = threadIdx.x;   // 256
    __shared__ float emb[2 * Hq];
    __shared__ float p[Hq];
    __shared__ float stats[2];

    if (tid < Hq) emb[tid] = g_psum[g * Hq + tid] / fmaxf(g_gcnt[g], 1.0f);
    else          emb[tid] = g_pmax[g * Hq + (tid - Hq)];
    __syncthreads();

    if (tid < Hq) {
        float t = bq1[tid];
        for (int k = 0; k < 2 * Hq; k++) t += emb[k] * Wq1[k * Hq + tid];
        p[tid] = t;
    }
    __syncthreads();

    if (tid == 0) {
        float s = 0.f;
        for (int j = 0; j < Hq; j++) s += p[j];
        float mu = s * (1.0f / 128.0f);
        float v = 0.f;
        for (int j = 0; j < Hq; j++) { float dd = p[j] - mu; v += dd * dd; }
        stats[0] = mu;
        stats[1] = rsqrtf(v * (1.0f / 128.0f) + 1e-5f);
    }
    __syncthreads();

    if (tid < Hq) {
        float y = (p[tid] - stats[0]) * stats[1] * gq[tid] + beq[tid];
        p[tid] = gelu_exact(y);
    }
    __syncthreads();

    float o = bq2[tid];
    for (int k = 0; k < Hq; k++) o += p[k] * Wq2[k * FOUTq + tid];
    out[g * FOUTq + tid] = o;
}

// ---------------- launch ----------------
extern "C" void kernel_launch(void* const* d_in, const int* in_sizes, int n_in,
                              void* d_out, int out_size)
{
    const float* x   = (const float*)d_in[0];
    const int*   ei  = (const int*)d_in[1];
    const int*   n2g = (const int*)d_in[2];
    const float* Wp  = (const float*)d_in[3];
    const float* bp  = (const float*)d_in[4];
    const float* Wq1 = (const float*)d_in[5];
    const float* bq1 = (const float*)d_in[6];
    const float* gq  = (const float*)d_in[7];
    const float* beq = (const float*)d_in[8];
    const float* Wq2 = (const float*)d_in[9];
    const float* bq2 = (const float*)d_in[10];
    float* out = (float*)d_out;

    float* ph = nullptr;
    void* pcnt = nullptr;
    cudaGetSymbolAddress((void**)&ph, g_h);
    cudaGetSymbolAddress(&pcnt, g_cnt_i);

    static cudaStream_t s2 = nullptr;
    static cudaEvent_t evA = nullptr, evB = nullptr, evC = nullptr;
    if (s2 == nullptr) {
        cudaStreamCreateWithFlags(&s2, cudaStreamNonBlocking);
        cudaEventCreateWithFlags(&evA, cudaEventDisableTiming);
        cudaEventCreateWithFlags(&evB, cudaEventDisableTiming);
        cudaEventCreateWithFlags(&evC, cudaEventDisableTiming);
    }

    const int NB_GEMM = (Nn + 127) / 128;
    const int NB_E    = (ETOT + 255) / 256;
    const int NB_AGG  = (Nn + 7) / 8;
    const int NB_POOL = (Nn + 255) / 256;

    // ---- side stream: CSR build ----
    cudaEventRecord(evA, 0);
    cudaStreamWaitEvent(s2, evA, 0);
    cudaMemsetAsync(pcnt, 0, Nn * sizeof(int), s2);
    hist_dst<<<NB_E, 256, 0, s2>>>(ei);
    scan_dl<<<NTILE, 256, 0, s2>>>();
    csr_fill<<<NB_E, 256, 0, s2>>>(ei);
    cudaEventRecord(evB, s2);

    // ---- main path ----
    gemm_proj<<<NB_GEMM, 256>>>(x, Wp, bp, ph, Nn);
    gemm_tf32<<<NB_GEMM, 256>>>(ph, (const float*)d_in[11],
                                (const float*)d_in[12], (const float*)d_in[13], Nn);

    cudaStreamWaitEvent(0, evB, 0);
    gat_agg_ln<<<NB_AGG, 256>>>((const float*)d_in[14], (const float*)d_in[15],
                                (const float*)d_in[16]);

    gemm_tf32<<<NB_GEMM, 256>>>(ph, (const float*)d_in[17],
                                (const float*)d_in[18], (const float*)d_in[19], Nn);
    gat_agg_ln<<<NB_AGG, 256>>>((const float*)d_in[20], (const float*)d_in[21],
                                (const float*)d_in[22]);

    // pooling setup late on side stream (keeps early profile window on hot kernels)
    pool_clear<<<(Gq * Hq + 255) / 256, 256, 0, s2>>>();
    cudaEventRecord(evC, s2);
    cudaStreamWaitEvent(0, evC, 0);
    pool_chunk<<<NB_POOL, 128>>>(n2g);
    final_mlp<<<Gq, 256>>>(Wq1, bq1, gq, beq, Wq2, bq2, out);
}